// round 2
// baseline (speedup 1.0000x reference)
#include <cuda_runtime.h>
#include <cstdint>
#include <cstddef>

#define BB 64          // batch
#define OUTC 384       // 3 levels * 128

// ---------------- scratch (static device globals; no runtime alloc) ----------------
__device__ float g_pts1[BB * 1024 * 3];
__device__ float g_pts2[BB * 512 * 3];
__device__ float g_z2[(size_t)BB * 2048 * 128];   // 64 MB, reused per level
__device__ float g_stats[12];                     // x,y,z, xx,xy,xz,yy,yz,zz
__device__ float g_w1f[3 * 64];                   // BN1-folded layer-1 weights
__device__ float g_b1f[64];
__device__ float g_zsum[128];
__device__ float g_zsq[128];
__device__ float g_s2[128];
__device__ float g_t2[128];

// ---------------- zero per-level accumulators (+ output once) ----------------
__global__ void k_zero(float* out, int zero_out) {
    int t = threadIdx.x;
    if (t < 12) g_stats[t] = 0.0f;
    if (t < 128) { g_zsum[t] = 0.0f; g_zsq[t] = 0.0f; }
    if (zero_out) {
        for (int i = t; i < BB * OUTC; i += blockDim.x) out[i] = 0.0f;
    }
}

// ---------------- point moments: sum p, sum p⊗p ----------------
__global__ void k_stats1(const float* __restrict__ pts, int P) {
    float s[9];
#pragma unroll
    for (int j = 0; j < 9; j++) s[j] = 0.0f;
    for (int i = blockIdx.x * blockDim.x + threadIdx.x; i < P; i += gridDim.x * blockDim.x) {
        float x = pts[(size_t)i * 3 + 0];
        float y = pts[(size_t)i * 3 + 1];
        float z = pts[(size_t)i * 3 + 2];
        s[0] += x; s[1] += y; s[2] += z;
        s[3] += x * x; s[4] += x * y; s[5] += x * z;
        s[6] += y * y; s[7] += y * z; s[8] += z * z;
    }
#pragma unroll
    for (int o = 16; o; o >>= 1) {
#pragma unroll
        for (int j = 0; j < 9; j++) s[j] += __shfl_xor_sync(0xffffffff, s[j], o);
    }
    if ((threadIdx.x & 31) == 0) {
#pragma unroll
        for (int j = 0; j < 9; j++) atomicAdd(&g_stats[j], s[j]);
    }
}

// ---------------- analytic BN1 -> folded layer-1 weights ----------------
__global__ void k_fin1(const float* __restrict__ w1, const float* __restrict__ b1,
                       const float* __restrict__ g1, const float* __restrict__ be1,
                       float invP) {
    int o = threadIdx.x;  // 64
    float mx = g_stats[0] * invP, my = g_stats[1] * invP, mz = g_stats[2] * invP;
    float Sxx = g_stats[3] * invP, Sxy = g_stats[4] * invP, Sxz = g_stats[5] * invP;
    float Syy = g_stats[6] * invP, Syz = g_stats[7] * invP, Szz = g_stats[8] * invP;
    float w0 = w1[o], w1_ = w1[64 + o], w2_ = w1[128 + o], b = b1[o];
    float mq = mx * w0 + my * w1_ + mz * w2_;
    float eq2 = Sxx * w0 * w0 + Syy * w1_ * w1_ + Szz * w2_ * w2_
              + 2.0f * (Sxy * w0 * w1_ + Sxz * w0 * w2_ + Syz * w1_ * w2_);
    float mean = mq + b;
    float var = eq2 - mq * mq;                 // var(q+b) = E[q^2]-E[q]^2
    float s = g1[o] * rsqrtf(var + 1e-5f);
    float t = be1[o] - mean * s;
    g_w1f[o] = w0 * s; g_w1f[64 + o] = w1_ * s; g_w1f[128 + o] = w2_ * s;
    g_b1f[o] = b * s + t;
}

// ---------------- fused: h1 = relu(p*w1f+b1f); z2 = h1*w2 + b2; store z2; accumulate stats --------
__global__ void __launch_bounds__(256) k_gemm2(const float* __restrict__ pts,
                                               const float* __restrict__ w2,
                                               const float* __restrict__ b2,
                                               float* __restrict__ z2out) {
    __shared__ float Ht[64 * 128];   // [k][p], reused as reduction buffer later
    __shared__ float w1s[192];
    __shared__ float b1s[64];
    int t = threadIdx.x;
    if (t < 192) w1s[t] = g_w1f[t];
    if (t < 64) b1s[t] = g_b1f[t];
    __syncthreads();

    // stage A: compute H (128 points x 64 channels), transposed into smem
    {
        int p = t >> 1, half = t & 1;
        size_t gp = (size_t)blockIdx.x * 128 + p;
        float x = pts[gp * 3 + 0], y = pts[gp * 3 + 1], z = pts[gp * 3 + 2];
        int c0 = half * 32;
#pragma unroll
        for (int cc = 0; cc < 32; cc++) {
            int c = c0 + cc;
            float h = fmaf(x, w1s[c], fmaf(y, w1s[64 + c], fmaf(z, w1s[128 + c], b1s[c])));
            Ht[c * 128 + p] = fmaxf(h, 0.0f);
        }
    }
    __syncthreads();

    // stage B: 128x128x64 GEMM, 8x8 register tiles
    int r = t >> 4, q = t & 15;
    int pr = r * 8, cq = q * 8;
    float acc[8][8];
#pragma unroll
    for (int i = 0; i < 8; i++)
#pragma unroll
        for (int j = 0; j < 8; j++) acc[i][j] = 0.0f;

#pragma unroll 4
    for (int k = 0; k < 64; k++) {
        float4 a0 = *(const float4*)&Ht[k * 128 + pr];
        float4 a1 = *(const float4*)&Ht[k * 128 + pr + 4];
        float4 w0 = __ldg((const float4*)&w2[k * 128 + cq]);
        float4 w1v = __ldg((const float4*)&w2[k * 128 + cq + 4]);
        float a[8] = {a0.x, a0.y, a0.z, a0.w, a1.x, a1.y, a1.z, a1.w};
        float w[8] = {w0.x, w0.y, w0.z, w0.w, w1v.x, w1v.y, w1v.z, w1v.w};
#pragma unroll
        for (int i = 0; i < 8; i++)
#pragma unroll
            for (int j = 0; j < 8; j++) acc[i][j] = fmaf(a[i], w[j], acc[i][j]);
    }

    // epilogue: add b2, store z2, accumulate per-channel sum / sumsq
    float bv[8];
#pragma unroll
    for (int j = 0; j < 8; j++) bv[j] = __ldg(&b2[cq + j]);
    float ls[8], lq[8];
#pragma unroll
    for (int j = 0; j < 8; j++) { ls[j] = 0.0f; lq[j] = 0.0f; }
    size_t gbase = ((size_t)blockIdx.x * 128 + pr) * 128 + cq;
#pragma unroll
    for (int i = 0; i < 8; i++) {
        float zr[8];
#pragma unroll
        for (int j = 0; j < 8; j++) {
            zr[j] = acc[i][j] + bv[j];
            ls[j] += zr[j];
            lq[j] += zr[j] * zr[j];
        }
        float4* dst = (float4*)&z2out[gbase + (size_t)i * 128];
        dst[0] = make_float4(zr[0], zr[1], zr[2], zr[3]);
        dst[1] = make_float4(zr[4], zr[5], zr[6], zr[7]);
    }

    __syncthreads();                 // done reading Ht; reuse as reduction buffer
    float* red = Ht;                 // [16][128]
    *(float4*)&red[r * 128 + cq] = make_float4(ls[0], ls[1], ls[2], ls[3]);
    *(float4*)&red[r * 128 + cq + 4] = make_float4(ls[4], ls[5], ls[6], ls[7]);
    __syncthreads();
    if (t < 128) {
        float s = 0.0f;
#pragma unroll
        for (int rr = 0; rr < 16; rr++) s += red[rr * 128 + t];
        atomicAdd(&g_zsum[t], s);
    }
    __syncthreads();
    *(float4*)&red[r * 128 + cq] = make_float4(lq[0], lq[1], lq[2], lq[3]);
    *(float4*)&red[r * 128 + cq + 4] = make_float4(lq[4], lq[5], lq[6], lq[7]);
    __syncthreads();
    if (t < 128) {
        float s = 0.0f;
#pragma unroll
        for (int rr = 0; rr < 16; rr++) s += red[rr * 128 + t];
        atomicAdd(&g_zsq[t], s);
    }
}

// ---------------- finalize BN2 affine ----------------
__global__ void k_fin2(const float* __restrict__ g2, const float* __restrict__ be2, float invP) {
    int c = threadIdx.x;  // 128
    float mean = g_zsum[c] * invP;
    float var = g_zsq[c] * invP - mean * mean;
    float s = g2[c] * rsqrtf(var + 1e-5f);
    g_s2[c] = s;
    g_t2[c] = be2[c] - mean * s;
}

// ---------------- BN2 + relu + global maxpool ----------------
__global__ void __launch_bounds__(128) k_bnmax(const float* __restrict__ z2,
                                               float* __restrict__ out, int N, int lv) {
    int c = threadIdx.x;            // 128 channels
    int b = blockIdx.y;
    int chunk = blockIdx.x;
    const float* zp = z2 + ((size_t)(b * N + chunk * 256)) * 128 + c;
    float s = g_s2[c], t = g_t2[c];
    float m = 0.0f;                 // relu floor
#pragma unroll 8
    for (int p = 0; p < 256; p++) {
        m = fmaxf(m, fmaf(zp[(size_t)p * 128], s, t));
    }
    atomicMax((int*)&out[b * OUTC + lv * 128 + c], __float_as_int(m));
}

// ---------------- farthest point sampling + gather (one block per batch) ----------------
template <int PPT>
__global__ void __launch_bounds__(256) k_fps(const float* __restrict__ pts,
                                             float* __restrict__ outp, int N, int m) {
    __shared__ float sx[2048], sy[2048], sz[2048];
    __shared__ float swv[2][8];
    __shared__ int swi[2][8];
    const float* base = pts + (size_t)blockIdx.x * N * 3;
    float* ob = outp + (size_t)blockIdx.x * m * 3;
    int t = threadIdx.x;
    int warp = t >> 5, lane = t & 31;

    float px[PPT], py[PPT], pz[PPT], mind[PPT];
#pragma unroll
    for (int j = 0; j < PPT; j++) {
        int n = t + j * 256;
        float x = base[n * 3 + 0], y = base[n * 3 + 1], z = base[n * 3 + 2];
        px[j] = x; py[j] = y; pz[j] = z;
        sx[n] = x; sy[n] = y; sz[n] = z;
        mind[j] = 3.4e38f;
    }
    __syncthreads();

    float cx = sx[0], cy = sy[0], cz = sz[0];   // idxs[0] = 0
    if (t == 0) { ob[0] = cx; ob[1] = cy; ob[2] = cz; }

    for (int i = 1; i < m; i++) {
        float bv = -1.0f;
        int bi = 0x7fffffff;
#pragma unroll
        for (int j = 0; j < PPT; j++) {
            float dx = px[j] - cx, dy = py[j] - cy, dz = pz[j] - cz;
            float d = fmaf(dz, dz, fmaf(dy, dy, dx * dx));
            float mm = fminf(mind[j], d);
            mind[j] = mm;
            if (mm > bv) { bv = mm; bi = t + j * 256; }
        }
        // warp butterfly argmax with smallest-index tie-break (portable: no redux.f32)
#pragma unroll
        for (int o = 16; o; o >>= 1) {
            float ov = __shfl_xor_sync(0xffffffff, bv, o);
            int oi = __shfl_xor_sync(0xffffffff, bi, o);
            if (ov > bv || (ov == bv && oi < bi)) { bv = ov; bi = oi; }
        }
        int par = i & 1;
        if (lane == 0) { swv[par][warp] = bv; swi[par][warp] = bi; }
        __syncthreads();
        float best = swv[par][0];
        int nxt = swi[par][0];
#pragma unroll
        for (int w = 1; w < 8; w++) {
            float v = swv[par][w];
            int ix = swi[par][w];
            if (v > best || (v == best && ix < nxt)) { best = v; nxt = ix; }
        }
        cx = sx[nxt]; cy = sy[nxt]; cz = sz[nxt];
        if (t == 0) { ob[i * 3 + 0] = cx; ob[i * 3 + 1] = cy; ob[i * 3 + 2] = cz; }
    }
}

// ---------------- host launcher ----------------
extern "C" void kernel_launch(void* const* d_in, const int* in_sizes, int n_in,
                              void* d_out, int out_size) {
    const float* points = (const float*)d_in[0];
    const float* w1 = (const float*)d_in[1];
    const float* b1 = (const float*)d_in[2];
    const float* g1 = (const float*)d_in[3];
    const float* be1 = (const float*)d_in[4];
    const float* w2 = (const float*)d_in[5];
    const float* b2 = (const float*)d_in[6];
    const float* g2 = (const float*)d_in[7];
    const float* be2 = (const float*)d_in[8];
    float* out = (float*)d_out;

    float *pts1, *pts2, *z2;
    cudaGetSymbolAddress((void**)&pts1, g_pts1);
    cudaGetSymbolAddress((void**)&pts2, g_pts2);
    cudaGetSymbolAddress((void**)&z2, g_z2);

    const float* ptsl[3] = {points, pts1, pts2};

    for (int lv = 0; lv < 3; lv++) {
        int N = 2048 >> lv;
        int P = BB * N;
        float invP = 1.0f / (float)P;

        k_zero<<<1, 512>>>(out, lv == 0 ? 1 : 0);
        k_stats1<<<132, 256>>>(ptsl[lv], P);
        k_fin1<<<1, 64>>>(w1 + lv * 192, b1 + lv * 64, g1 + lv * 64, be1 + lv * 64, invP);
        k_gemm2<<<P / 128, 256>>>(ptsl[lv], w2 + lv * 8192, b2 + lv * 128, z2);
        k_fin2<<<1, 128>>>(g2 + lv * 128, be2 + lv * 128, invP);
        k_bnmax<<<dim3(N / 256, BB), 128>>>(z2, out, N, lv);

        if (lv == 0) k_fps<8><<<BB, 256>>>(points, pts1, 2048, 1024);
        else if (lv == 1) k_fps<4><<<BB, 256>>>(pts1, pts2, 1024, 512);
    }
}

// round 3
// speedup vs baseline: 1.4385x; 1.4385x over previous
#include <cuda_runtime.h>
#include <cstdint>
#include <cstddef>

#define BB 64          // batch
#define OUTC 384       // 3 levels * 128

// ---------------- scratch (static device globals; no runtime alloc) ----------------
__device__ float g_pts1[BB * 1024 * 3];
__device__ float g_pts2[BB * 512 * 3];
__device__ float g_z2[(size_t)BB * 2048 * 128];   // 64 MB, reused per level
__device__ float g_stats[12];                     // x,y,z, xx,xy,xz,yy,yz,zz
__device__ float g_w1f[3 * 64];                   // BN1-folded layer-1 weights
__device__ float g_b1f[64];
__device__ float g_zsum[128];
__device__ float g_zsq[128];
__device__ float g_s2[128];
__device__ float g_t2[128];

// ---------------- zero per-level accumulators (+ output once) ----------------
__global__ void k_zero(float* out, int zero_out) {
    int t = threadIdx.x;
    if (t < 12) g_stats[t] = 0.0f;
    if (t < 128) { g_zsum[t] = 0.0f; g_zsq[t] = 0.0f; }
    if (zero_out) {
        for (int i = t; i < BB * OUTC; i += blockDim.x) out[i] = 0.0f;
    }
}

// ---------------- point moments: sum p, sum p⊗p ----------------
__global__ void k_stats1(const float* __restrict__ pts, int P) {
    float s[9];
#pragma unroll
    for (int j = 0; j < 9; j++) s[j] = 0.0f;
    for (int i = blockIdx.x * blockDim.x + threadIdx.x; i < P; i += gridDim.x * blockDim.x) {
        float x = pts[(size_t)i * 3 + 0];
        float y = pts[(size_t)i * 3 + 1];
        float z = pts[(size_t)i * 3 + 2];
        s[0] += x; s[1] += y; s[2] += z;
        s[3] += x * x; s[4] += x * y; s[5] += x * z;
        s[6] += y * y; s[7] += y * z; s[8] += z * z;
    }
#pragma unroll
    for (int o = 16; o; o >>= 1) {
#pragma unroll
        for (int j = 0; j < 9; j++) s[j] += __shfl_xor_sync(0xffffffff, s[j], o);
    }
    if ((threadIdx.x & 31) == 0) {
#pragma unroll
        for (int j = 0; j < 9; j++) atomicAdd(&g_stats[j], s[j]);
    }
}

// ---------------- analytic BN1 -> folded layer-1 weights ----------------
__global__ void k_fin1(const float* __restrict__ w1, const float* __restrict__ b1,
                       const float* __restrict__ g1, const float* __restrict__ be1,
                       float invP) {
    int o = threadIdx.x;  // 64
    float mx = g_stats[0] * invP, my = g_stats[1] * invP, mz = g_stats[2] * invP;
    float Sxx = g_stats[3] * invP, Sxy = g_stats[4] * invP, Sxz = g_stats[5] * invP;
    float Syy = g_stats[6] * invP, Syz = g_stats[7] * invP, Szz = g_stats[8] * invP;
    float w0 = w1[o], w1_ = w1[64 + o], w2_ = w1[128 + o], b = b1[o];
    float mq = mx * w0 + my * w1_ + mz * w2_;
    float eq2 = Sxx * w0 * w0 + Syy * w1_ * w1_ + Szz * w2_ * w2_
              + 2.0f * (Sxy * w0 * w1_ + Sxz * w0 * w2_ + Syz * w1_ * w2_);
    float mean = mq + b;
    float var = eq2 - mq * mq;                 // var(q+b) = E[q^2]-E[q]^2
    float s = g1[o] * rsqrtf(var + 1e-5f);
    float t = be1[o] - mean * s;
    g_w1f[o] = w0 * s; g_w1f[64 + o] = w1_ * s; g_w1f[128 + o] = w2_ * s;
    g_b1f[o] = b * s + t;
}

// ---------------- fused: h1 = relu(p*w1f+b1f); z2 = h1*w2 + b2; store z2; accumulate stats --------
__global__ void __launch_bounds__(256) k_gemm2(const float* __restrict__ pts,
                                               const float* __restrict__ w2,
                                               const float* __restrict__ b2,
                                               float* __restrict__ z2out) {
    __shared__ float Ht[64 * 128];   // [k][p], reused as reduction buffer later
    __shared__ float w1s[192];
    __shared__ float b1s[64];
    int t = threadIdx.x;
    if (t < 192) w1s[t] = g_w1f[t];
    if (t < 64) b1s[t] = g_b1f[t];
    __syncthreads();

    // stage A: compute H (128 points x 64 channels), transposed into smem
    {
        int p = t >> 1, half = t & 1;
        size_t gp = (size_t)blockIdx.x * 128 + p;
        float x = pts[gp * 3 + 0], y = pts[gp * 3 + 1], z = pts[gp * 3 + 2];
        int c0 = half * 32;
#pragma unroll
        for (int cc = 0; cc < 32; cc++) {
            int c = c0 + cc;
            float h = fmaf(x, w1s[c], fmaf(y, w1s[64 + c], fmaf(z, w1s[128 + c], b1s[c])));
            Ht[c * 128 + p] = fmaxf(h, 0.0f);
        }
    }
    __syncthreads();

    // stage B: 128x128x64 GEMM, 8x8 register tiles
    int r = t >> 4, q = t & 15;
    int pr = r * 8, cq = q * 8;
    float acc[8][8];
#pragma unroll
    for (int i = 0; i < 8; i++)
#pragma unroll
        for (int j = 0; j < 8; j++) acc[i][j] = 0.0f;

#pragma unroll 4
    for (int k = 0; k < 64; k++) {
        float4 a0 = *(const float4*)&Ht[k * 128 + pr];
        float4 a1 = *(const float4*)&Ht[k * 128 + pr + 4];
        float4 w0 = __ldg((const float4*)&w2[k * 128 + cq]);
        float4 w1v = __ldg((const float4*)&w2[k * 128 + cq + 4]);
        float a[8] = {a0.x, a0.y, a0.z, a0.w, a1.x, a1.y, a1.z, a1.w};
        float w[8] = {w0.x, w0.y, w0.z, w0.w, w1v.x, w1v.y, w1v.z, w1v.w};
#pragma unroll
        for (int i = 0; i < 8; i++)
#pragma unroll
            for (int j = 0; j < 8; j++) acc[i][j] = fmaf(a[i], w[j], acc[i][j]);
    }

    // epilogue: add b2, store z2, accumulate per-channel sum / sumsq
    float bv[8];
#pragma unroll
    for (int j = 0; j < 8; j++) bv[j] = __ldg(&b2[cq + j]);
    float ls[8], lq[8];
#pragma unroll
    for (int j = 0; j < 8; j++) { ls[j] = 0.0f; lq[j] = 0.0f; }
    size_t gbase = ((size_t)blockIdx.x * 128 + pr) * 128 + cq;
#pragma unroll
    for (int i = 0; i < 8; i++) {
        float zr[8];
#pragma unroll
        for (int j = 0; j < 8; j++) {
            zr[j] = acc[i][j] + bv[j];
            ls[j] += zr[j];
            lq[j] += zr[j] * zr[j];
        }
        float4* dst = (float4*)&z2out[gbase + (size_t)i * 128];
        dst[0] = make_float4(zr[0], zr[1], zr[2], zr[3]);
        dst[1] = make_float4(zr[4], zr[5], zr[6], zr[7]);
    }

    __syncthreads();                 // done reading Ht; reuse as reduction buffer
    float* red = Ht;                 // [16][128]
    *(float4*)&red[r * 128 + cq] = make_float4(ls[0], ls[1], ls[2], ls[3]);
    *(float4*)&red[r * 128 + cq + 4] = make_float4(ls[4], ls[5], ls[6], ls[7]);
    __syncthreads();
    if (t < 128) {
        float s = 0.0f;
#pragma unroll
        for (int rr = 0; rr < 16; rr++) s += red[rr * 128 + t];
        atomicAdd(&g_zsum[t], s);
    }
    __syncthreads();
    *(float4*)&red[r * 128 + cq] = make_float4(lq[0], lq[1], lq[2], lq[3]);
    *(float4*)&red[r * 128 + cq + 4] = make_float4(lq[4], lq[5], lq[6], lq[7]);
    __syncthreads();
    if (t < 128) {
        float s = 0.0f;
#pragma unroll
        for (int rr = 0; rr < 16; rr++) s += red[rr * 128 + t];
        atomicAdd(&g_zsq[t], s);
    }
}

// ---------------- finalize BN2 affine ----------------
__global__ void k_fin2(const float* __restrict__ g2, const float* __restrict__ be2, float invP) {
    int c = threadIdx.x;  // 128
    float mean = g_zsum[c] * invP;
    float var = g_zsq[c] * invP - mean * mean;
    float s = g2[c] * rsqrtf(var + 1e-5f);
    g_s2[c] = s;
    g_t2[c] = be2[c] - mean * s;
}

// ---------------- BN2 + relu + global maxpool ----------------
__global__ void __launch_bounds__(128) k_bnmax(const float* __restrict__ z2,
                                               float* __restrict__ out, int N, int lv) {
    int c = threadIdx.x;            // 128 channels
    int b = blockIdx.y;
    int chunk = blockIdx.x;
    const float* zp = z2 + ((size_t)(b * N + chunk * 256)) * 128 + c;
    float s = g_s2[c], t = g_t2[c];
    float m = 0.0f;                 // relu floor
#pragma unroll 8
    for (int p = 0; p < 256; p++) {
        m = fmaxf(m, fmaf(zp[(size_t)p * 128], s, t));
    }
    atomicMax((int*)&out[b * OUTC + lv * 128 + c], __float_as_int(m));
}

// ---------------- farthest point sampling + gather (one block per batch) ----------------
// u64-packed argmax: (dist_bits << 32) | ~index. Distances >= 0 so float bits
// are order-preserving; ~index makes max() pick the SMALLEST index on ties,
// matching jnp.argmax first-occurrence semantics.
template <int PPT, int NW>
__global__ void __launch_bounds__(NW * 32) k_fps(const float* __restrict__ pts,
                                                 float* __restrict__ outp, int N, int m) {
    __shared__ float sx[2048], sy[2048], sz[2048];
    __shared__ unsigned long long swb[2][NW];
    const int T = NW * 32;
    const float* base = pts + (size_t)blockIdx.x * N * 3;
    float* ob = outp + (size_t)blockIdx.x * m * 3;
    int t = threadIdx.x;
    int warp = t >> 5, lane = t & 31;

    float px[PPT], py[PPT], pz[PPT], mind[PPT];
#pragma unroll
    for (int j = 0; j < PPT; j++) {
        int n = t + j * T;
        float x = base[n * 3 + 0], y = base[n * 3 + 1], z = base[n * 3 + 2];
        px[j] = x; py[j] = y; pz[j] = z;
        sx[n] = x; sy[n] = y; sz[n] = z;
        mind[j] = 3.4e38f;
    }
    __syncthreads();

    float cx = sx[0], cy = sy[0], cz = sz[0];   // idxs[0] = 0
    if (t == 0) { ob[0] = cx; ob[1] = cy; ob[2] = cz; }

    for (int i = 1; i < m; i++) {
        unsigned long long cand[PPT];
#pragma unroll
        for (int j = 0; j < PPT; j++) {
            float dx = px[j] - cx, dy = py[j] - cy, dz = pz[j] - cz;
            float d = fmaf(dz, dz, fmaf(dy, dy, dx * dx));
            float mm = fminf(mind[j], d);
            mind[j] = mm;
            cand[j] = ((unsigned long long)__float_as_uint(mm) << 32)
                    | (unsigned)(~(t + j * T));
        }
        // balanced tree over per-thread candidates (depth log2(PPT))
#pragma unroll
        for (int s = PPT >> 1; s; s >>= 1)
#pragma unroll
            for (int j = 0; j < s; j++)
                cand[j] = cand[j] > cand[j + s] ? cand[j] : cand[j + s];

        unsigned long long best = cand[0];
#pragma unroll
        for (int o = 16; o; o >>= 1) {
            unsigned long long ov = __shfl_xor_sync(0xffffffffu, best, o);
            best = ov > best ? ov : best;
        }
        int par = i & 1;
        if (lane == 0) swb[par][warp] = best;
        __syncthreads();
        unsigned long long b = swb[par][0];
#pragma unroll
        for (int w = 1; w < NW; w++) {
            unsigned long long v = swb[par][w];
            b = v > b ? v : b;
        }
        int nxt = (int)(~(unsigned)(b & 0xffffffffu));
        cx = sx[nxt]; cy = sy[nxt]; cz = sz[nxt];
        if (t == 0) { ob[i * 3 + 0] = cx; ob[i * 3 + 1] = cy; ob[i * 3 + 2] = cz; }
    }
}

// ---------------- host launcher ----------------
extern "C" void kernel_launch(void* const* d_in, const int* in_sizes, int n_in,
                              void* d_out, int out_size) {
    const float* points = (const float*)d_in[0];
    const float* w1 = (const float*)d_in[1];
    const float* b1 = (const float*)d_in[2];
    const float* g1 = (const float*)d_in[3];
    const float* be1 = (const float*)d_in[4];
    const float* w2 = (const float*)d_in[5];
    const float* b2 = (const float*)d_in[6];
    const float* g2 = (const float*)d_in[7];
    const float* be2 = (const float*)d_in[8];
    float* out = (float*)d_out;

    float *pts1, *pts2, *z2;
    cudaGetSymbolAddress((void**)&pts1, g_pts1);
    cudaGetSymbolAddress((void**)&pts2, g_pts2);
    cudaGetSymbolAddress((void**)&z2, g_z2);

    // one-time host resources (streams/events are not device memory)
    static cudaStream_t s_fps = nullptr;
    static cudaEvent_t e_root = nullptr, e_fps0 = nullptr, e_fps1 = nullptr;
    if (!s_fps) {
        cudaStreamCreateWithFlags(&s_fps, cudaStreamNonBlocking);
        cudaEventCreateWithFlags(&e_root, cudaEventDisableTiming);
        cudaEventCreateWithFlags(&e_fps0, cudaEventDisableTiming);
        cudaEventCreateWithFlags(&e_fps1, cudaEventDisableTiming);
    }

    const float* ptsl[3] = {points, pts1, pts2};

    // ---- fork: FPS chain runs concurrently with level compute ----
    cudaEventRecord(e_root, 0);
    cudaStreamWaitEvent(s_fps, e_root, 0);
    k_fps<16, 4><<<BB, 128, 0, s_fps>>>(points, pts1, 2048, 1024);
    cudaEventRecord(e_fps0, s_fps);
    k_fps<8, 4><<<BB, 128, 0, s_fps>>>(pts1, pts2, 1024, 512);
    cudaEventRecord(e_fps1, s_fps);

    for (int lv = 0; lv < 3; lv++) {
        int N = 2048 >> lv;
        int P = BB * N;
        float invP = 1.0f / (float)P;

        if (lv == 1) cudaStreamWaitEvent(0, e_fps0, 0);   // pts1 ready
        if (lv == 2) cudaStreamWaitEvent(0, e_fps1, 0);   // pts2 ready (joins fps stream)

        k_zero<<<1, 512>>>(out, lv == 0 ? 1 : 0);
        k_stats1<<<132, 256>>>(ptsl[lv], P);
        k_fin1<<<1, 64>>>(w1 + lv * 192, b1 + lv * 64, g1 + lv * 64, be1 + lv * 64, invP);
        k_gemm2<<<P / 128, 256>>>(ptsl[lv], w2 + lv * 8192, b2 + lv * 128, z2);
        k_fin2<<<1, 128>>>(g2 + lv * 128, be2 + lv * 128, invP);
        k_bnmax<<<dim3(N / 256, BB), 128>>>(z2, out, N, lv);
    }
}

// round 5
// speedup vs baseline: 1.6896x; 1.1746x over previous
#include <cuda_runtime.h>
#include <cstdint>
#include <cstddef>

#define BB 64          // batch
#define OUTC 384       // 3 levels * 128

// ---------------- scratch (static device globals; no runtime alloc) ----------------
__device__ __align__(16) float g_pts1[BB * 1024 * 3];
__device__ __align__(16) float g_pts2[BB * 512 * 3];
__device__ float g_z2[(size_t)BB * 2048 * 128];   // 64 MB, reused per level
__device__ float g_stats[3][12];                  // per level: x,y,z, xx,xy,xz,yy,yz,zz
__device__ float g_w1f[3 * 64];                   // BN1-folded layer-1 weights
__device__ float g_b1f[64];
__device__ float g_zsum[3][128];
__device__ float g_zsq[3][128];
__device__ float g_s2[128];
__device__ float g_t2[128];

// ---------------- one-time zero of all accumulators + output ----------------
__global__ void k_init(float* out) {
    int i = blockIdx.x * blockDim.x + threadIdx.x;
    for (int k = i; k < BB * OUTC; k += gridDim.x * blockDim.x) out[k] = 0.0f;
    if (blockIdx.x == 0) {
        // zero ALL 3*128 entries of both accumulators (grid-stride: blockDim may be < 384)
        for (int t = threadIdx.x; t < 3 * 128; t += blockDim.x) {
            ((float*)g_zsum)[t] = 0.0f;
            ((float*)g_zsq)[t] = 0.0f;
        }
        for (int t = threadIdx.x; t < 36; t += blockDim.x)
            ((float*)g_stats)[t] = 0.0f;
    }
}

// ---------------- point moments: sum p, sum p⊗p (vectorized: 3xfloat4 = 4 points) -------
__global__ void k_stats1(const float4* __restrict__ p4, int nq, float* __restrict__ stats) {
    float s[9];
#pragma unroll
    for (int j = 0; j < 9; j++) s[j] = 0.0f;
    for (int i = blockIdx.x * blockDim.x + threadIdx.x; i < nq; i += gridDim.x * blockDim.x) {
        float4 a = __ldg(&p4[(size_t)i * 3 + 0]);
        float4 b = __ldg(&p4[(size_t)i * 3 + 1]);
        float4 c = __ldg(&p4[(size_t)i * 3 + 2]);
        // points: (a.x,a.y,a.z) (a.w,b.x,b.y) (b.z,b.w,c.x) (c.y,c.z,c.w)
#define ACC(X, Y, Z)                                        \
        { float x = (X), y = (Y), z = (Z);                  \
          s[0] += x; s[1] += y; s[2] += z;                  \
          s[3] += x * x; s[4] += x * y; s[5] += x * z;      \
          s[6] += y * y; s[7] += y * z; s[8] += z * z; }
        ACC(a.x, a.y, a.z) ACC(a.w, b.x, b.y) ACC(b.z, b.w, c.x) ACC(c.y, c.z, c.w)
#undef ACC
    }
#pragma unroll
    for (int o = 16; o; o >>= 1) {
#pragma unroll
        for (int j = 0; j < 9; j++) s[j] += __shfl_xor_sync(0xffffffff, s[j], o);
    }
    if ((threadIdx.x & 31) == 0) {
#pragma unroll
        for (int j = 0; j < 9; j++) atomicAdd(&stats[j], s[j]);
    }
}

// ---------------- analytic BN1 -> folded layer-1 weights ----------------
__global__ void k_fin1(const float* __restrict__ w1, const float* __restrict__ b1,
                       const float* __restrict__ g1, const float* __restrict__ be1,
                       const float* __restrict__ stats, float invP) {
    int o = threadIdx.x;  // 64
    float mx = stats[0] * invP, my = stats[1] * invP, mz = stats[2] * invP;
    float Sxx = stats[3] * invP, Sxy = stats[4] * invP, Sxz = stats[5] * invP;
    float Syy = stats[6] * invP, Syz = stats[7] * invP, Szz = stats[8] * invP;
    float w0 = w1[o], w1_ = w1[64 + o], w2_ = w1[128 + o], b = b1[o];
    float mq = mx * w0 + my * w1_ + mz * w2_;
    float eq2 = Sxx * w0 * w0 + Syy * w1_ * w1_ + Szz * w2_ * w2_
              + 2.0f * (Sxy * w0 * w1_ + Sxz * w0 * w2_ + Syz * w1_ * w2_);
    float mean = mq + b;
    float var = eq2 - mq * mq;                 // var(q+b) = E[q^2]-E[q]^2
    float s = g1[o] * rsqrtf(var + 1e-5f);
    float t = be1[o] - mean * s;
    g_w1f[o] = w0 * s; g_w1f[64 + o] = w1_ * s; g_w1f[128 + o] = w2_ * s;
    g_b1f[o] = b * s + t;
}

// ---------------- fused: h1 = relu(p*w1f+b1f); z2 = h1*w2 + b2; store z2; accumulate stats --------
__global__ void __launch_bounds__(256) k_gemm2(const float* __restrict__ pts,
                                               const float* __restrict__ w2,
                                               const float* __restrict__ b2,
                                               float* __restrict__ z2out,
                                               float* __restrict__ zsum,
                                               float* __restrict__ zsq) {
    __shared__ float Ht[64 * 128];   // [k][p], reused as reduction buffer later
    __shared__ float w1s[192];
    __shared__ float b1s[64];
    int t = threadIdx.x;
    if (t < 192) w1s[t] = g_w1f[t];
    if (t < 64) b1s[t] = g_b1f[t];
    __syncthreads();

    // stage A: compute H (128 points x 64 channels), transposed into smem
    {
        int p = t >> 1, half = t & 1;
        size_t gp = (size_t)blockIdx.x * 128 + p;
        float x = pts[gp * 3 + 0], y = pts[gp * 3 + 1], z = pts[gp * 3 + 2];
        int c0 = half * 32;
#pragma unroll
        for (int cc = 0; cc < 32; cc++) {
            int c = c0 + cc;
            float h = fmaf(x, w1s[c], fmaf(y, w1s[64 + c], fmaf(z, w1s[128 + c], b1s[c])));
            Ht[c * 128 + p] = fmaxf(h, 0.0f);
        }
    }
    __syncthreads();

    // stage B: 128x128x64 GEMM, 8x8 register tiles
    int r = t >> 4, q = t & 15;
    int pr = r * 8, cq = q * 8;
    float acc[8][8];
#pragma unroll
    for (int i = 0; i < 8; i++)
#pragma unroll
        for (int j = 0; j < 8; j++) acc[i][j] = 0.0f;

#pragma unroll 4
    for (int k = 0; k < 64; k++) {
        float4 a0 = *(const float4*)&Ht[k * 128 + pr];
        float4 a1 = *(const float4*)&Ht[k * 128 + pr + 4];
        float4 w0 = __ldg((const float4*)&w2[k * 128 + cq]);
        float4 w1v = __ldg((const float4*)&w2[k * 128 + cq + 4]);
        float a[8] = {a0.x, a0.y, a0.z, a0.w, a1.x, a1.y, a1.z, a1.w};
        float w[8] = {w0.x, w0.y, w0.z, w0.w, w1v.x, w1v.y, w1v.z, w1v.w};
#pragma unroll
        for (int i = 0; i < 8; i++)
#pragma unroll
            for (int j = 0; j < 8; j++) acc[i][j] = fmaf(a[i], w[j], acc[i][j]);
    }

    // epilogue: add b2, store z2, accumulate per-channel sum / sumsq
    float bv[8];
#pragma unroll
    for (int j = 0; j < 8; j++) bv[j] = __ldg(&b2[cq + j]);
    float ls[8], lq[8];
#pragma unroll
    for (int j = 0; j < 8; j++) { ls[j] = 0.0f; lq[j] = 0.0f; }
    size_t gbase = ((size_t)blockIdx.x * 128 + pr) * 128 + cq;
#pragma unroll
    for (int i = 0; i < 8; i++) {
        float zr[8];
#pragma unroll
        for (int j = 0; j < 8; j++) {
            zr[j] = acc[i][j] + bv[j];
            ls[j] += zr[j];
            lq[j] += zr[j] * zr[j];
        }
        float4* dst = (float4*)&z2out[gbase + (size_t)i * 128];
        dst[0] = make_float4(zr[0], zr[1], zr[2], zr[3]);
        dst[1] = make_float4(zr[4], zr[5], zr[6], zr[7]);
    }

    __syncthreads();                 // done reading Ht; reuse as reduction buffer
    float* red = Ht;                 // [16][128]
    *(float4*)&red[r * 128 + cq] = make_float4(ls[0], ls[1], ls[2], ls[3]);
    *(float4*)&red[r * 128 + cq + 4] = make_float4(ls[4], ls[5], ls[6], ls[7]);
    __syncthreads();
    if (t < 128) {
        float s = 0.0f;
#pragma unroll
        for (int rr = 0; rr < 16; rr++) s += red[rr * 128 + t];
        atomicAdd(&zsum[t], s);
    }
    __syncthreads();
    *(float4*)&red[r * 128 + cq] = make_float4(lq[0], lq[1], lq[2], lq[3]);
    *(float4*)&red[r * 128 + cq + 4] = make_float4(lq[4], lq[5], lq[6], lq[7]);
    __syncthreads();
    if (t < 128) {
        float s = 0.0f;
#pragma unroll
        for (int rr = 0; rr < 16; rr++) s += red[rr * 128 + t];
        atomicAdd(&zsq[t], s);
    }
}

// ---------------- finalize BN2 affine ----------------
__global__ void k_fin2(const float* __restrict__ g2, const float* __restrict__ be2,
                       const float* __restrict__ zsum, const float* __restrict__ zsq,
                       float invP) {
    int c = threadIdx.x;  // 128
    float mean = zsum[c] * invP;
    float var = zsq[c] * invP - mean * mean;
    float s = g2[c] * rsqrtf(var + 1e-5f);
    g_s2[c] = s;
    g_t2[c] = be2[c] - mean * s;
}

// ---------------- BN2 + relu + global maxpool ----------------
__global__ void __launch_bounds__(128) k_bnmax(const float* __restrict__ z2,
                                               float* __restrict__ out, int N, int lv) {
    int c = threadIdx.x;            // 128 channels
    int b = blockIdx.y;
    int chunk = blockIdx.x;
    const float* zp = z2 + ((size_t)(b * N + chunk * 256)) * 128 + c;
    float s = g_s2[c], t = g_t2[c];
    float m = 0.0f;                 // relu floor
#pragma unroll 8
    for (int p = 0; p < 256; p++) {
        m = fmaxf(m, fmaf(zp[(size_t)p * 128], s, t));
    }
    atomicMax((int*)&out[b * OUTC + lv * 128 + c], __float_as_int(m));
}

// ---------------- farthest point sampling + gather (one block per batch) ----------------
// Warp argmax via integer redux.sync (sm_80+): distances are >=0 so float bits are
// order-preserving as u32. Tie-break = smallest point index (jnp.argmax semantics):
// within thread: strict >, thread's indices ascending; within warp: reduce_min over
// indices matching the warp max; across warps: u64 max of (distbits<<32)|~idx.
template <int PPT, int NW>
__global__ void __launch_bounds__(NW * 32) k_fps(const float* __restrict__ pts,
                                                 float* __restrict__ outp, int N, int m) {
    __shared__ float sx[2048], sy[2048], sz[2048];
    __shared__ unsigned long long swb[2][NW];
    const int T = NW * 32;
    const float* base = pts + (size_t)blockIdx.x * N * 3;
    float* ob = outp + (size_t)blockIdx.x * m * 3;
    int t = threadIdx.x;

    float px[PPT], py[PPT], pz[PPT], mind[PPT];
#pragma unroll
    for (int j = 0; j < PPT; j++) {
        int n = t + j * T;
        float x = base[n * 3 + 0], y = base[n * 3 + 1], z = base[n * 3 + 2];
        px[j] = x; py[j] = y; pz[j] = z;
        sx[n] = x; sy[n] = y; sz[n] = z;
        mind[j] = 3.4e38f;
    }
    __syncthreads();

    float cx = sx[0], cy = sy[0], cz = sz[0];   // idxs[0] = 0
    if (t == 0) { ob[0] = cx; ob[1] = cy; ob[2] = cz; }

    for (int i = 1; i < m; i++) {
        float mv = -1.0f;
        int bi = 0;
#pragma unroll
        for (int j = 0; j < PPT; j++) {
            float dx = px[j] - cx, dy = py[j] - cy, dz = pz[j] - cz;
            float d = fmaf(dz, dz, fmaf(dy, dy, dx * dx));
            float mm = fminf(mind[j], d);
            mind[j] = mm;
            if (mm > mv) { mv = mm; bi = t + j * T; }   // strict > keeps smallest j
        }
        unsigned mvb = __float_as_uint(mv);
        unsigned wmax = __reduce_max_sync(0xffffffffu, mvb);
        unsigned cidx = (mvb == wmax) ? (unsigned)bi : 0xffffffffu;
        unsigned widx = __reduce_min_sync(0xffffffffu, cidx);
        int par = i & 1;
        if ((t & 31) == 0)
            swb[par][t >> 5] = ((unsigned long long)wmax << 32) | (unsigned)(~widx);
        __syncthreads();
        unsigned long long b = swb[par][0];
#pragma unroll
        for (int w = 1; w < NW; w++) {
            unsigned long long v = swb[par][w];
            b = v > b ? v : b;
        }
        int nxt = (int)(~(unsigned)(b & 0xffffffffu));
        cx = sx[nxt]; cy = sy[nxt]; cz = sz[nxt];
        if (t == 0) { ob[i * 3 + 0] = cx; ob[i * 3 + 1] = cy; ob[i * 3 + 2] = cz; }
    }
}

// ---------------- host launcher ----------------
extern "C" void kernel_launch(void* const* d_in, const int* in_sizes, int n_in,
                              void* d_out, int out_size) {
    const float* points = (const float*)d_in[0];
    const float* w1 = (const float*)d_in[1];
    const float* b1 = (const float*)d_in[2];
    const float* g1 = (const float*)d_in[3];
    const float* be1 = (const float*)d_in[4];
    const float* w2 = (const float*)d_in[5];
    const float* b2 = (const float*)d_in[6];
    const float* g2 = (const float*)d_in[7];
    const float* be2 = (const float*)d_in[8];
    float* out = (float*)d_out;

    float *pts1, *pts2, *z2, *statsb, *zsumb, *zsqb;
    cudaGetSymbolAddress((void**)&pts1, g_pts1);
    cudaGetSymbolAddress((void**)&pts2, g_pts2);
    cudaGetSymbolAddress((void**)&z2, g_z2);
    cudaGetSymbolAddress((void**)&statsb, g_stats);
    cudaGetSymbolAddress((void**)&zsumb, g_zsum);
    cudaGetSymbolAddress((void**)&zsqb, g_zsq);

    // one-time host resources (streams/events are not device memory)
    static cudaStream_t s_fps = nullptr;
    static cudaEvent_t e_root = nullptr, e_fps0 = nullptr, e_fps1 = nullptr;
    if (!s_fps) {
        cudaStreamCreateWithFlags(&s_fps, cudaStreamNonBlocking);
        cudaEventCreateWithFlags(&e_root, cudaEventDisableTiming);
        cudaEventCreateWithFlags(&e_fps0, cudaEventDisableTiming);
        cudaEventCreateWithFlags(&e_fps1, cudaEventDisableTiming);
    }

    const float* ptsl[3] = {points, pts1, pts2};

    k_init<<<96, 256>>>(out);

    // ---- fork: FPS chain runs concurrently with level compute ----
    cudaEventRecord(e_root, 0);
    cudaStreamWaitEvent(s_fps, e_root, 0);
    k_fps<8, 8><<<BB, 256, 0, s_fps>>>(points, pts1, 2048, 1024);
    cudaEventRecord(e_fps0, s_fps);
    k_fps<4, 8><<<BB, 256, 0, s_fps>>>(pts1, pts2, 1024, 512);
    cudaEventRecord(e_fps1, s_fps);

    for (int lv = 0; lv < 3; lv++) {
        int N = 2048 >> lv;
        int P = BB * N;
        float invP = 1.0f / (float)P;

        if (lv == 1) cudaStreamWaitEvent(0, e_fps0, 0);   // pts1 ready
        if (lv == 2) cudaStreamWaitEvent(0, e_fps1, 0);   // pts2 ready

        int nq = P / 4;
        int sgrid = nq / 256 < 128 ? nq / 256 : 128;
        k_stats1<<<sgrid, 256>>>((const float4*)ptsl[lv], nq, statsb + lv * 12);
        k_fin1<<<1, 64>>>(w1 + lv * 192, b1 + lv * 64, g1 + lv * 64, be1 + lv * 64,
                          statsb + lv * 12, invP);
        k_gemm2<<<P / 128, 256>>>(ptsl[lv], w2 + lv * 8192, b2 + lv * 128, z2,
                                  zsumb + lv * 128, zsqb + lv * 128);
        k_fin2<<<1, 128>>>(g2 + lv * 128, be2 + lv * 128,
                           zsumb + lv * 128, zsqb + lv * 128, invP);
        k_bnmax<<<dim3(N / 256, BB), 128>>>(z2, out, N, lv);
    }
}